// round 3
// baseline (speedup 1.0000x reference)
#include <cuda_runtime.h>
#include <cuda_fp16.h>
#include <cstdint>

// ---------------------------------------------------------------------------
// Problem: out[b,o,hw] = sum_c W[o,c] * relu(x[b,c,hw]*scale[c]+shift[c])
// GEMM: M = 256*49 = 12544 (rows b*49+hw), N = 192, K = 2112.
// Tensor path: mma.sync m16n8k16 fp16 (sm_80 feature set — compiles on plain
// sm_103 target; tcgen05 is 'a'-gated and rejected by this harness's ptxas).
// ---------------------------------------------------------------------------
constexpr int CIN   = 2112;
constexpr int COUT  = 192;
constexpr int HWSZ  = 49;
constexpr int M_TOTAL = 256 * HWSZ;   // 12544
constexpr int BM = 128;
constexpr int BK = 32;
constexpr int NKT = CIN / BK;         // 66
constexpr int GRID_M = M_TOTAL / BM;  // 98

// SMEM: fp16 tiles, row stride 40 halves (32 + 8 pad -> 20 banks, gcd(20,32)=4:
// conflict-free for both the STS patterns and the mma fragment LDS patterns).
constexpr int STRIDE_B = 80;                    // bytes per row (40 halves)
constexpr int A_STAGE  = BM * STRIDE_B;         // 10240 B
constexpr int B_STAGE  = COUT * STRIDE_B;       // 15360 B
constexpr int SMEM_B0  = 2 * A_STAGE;           // 20480
constexpr int SMEM_TOTAL = 2 * A_STAGE + 2 * B_STAGE;  // 51200 B

__device__ __align__(16) float g_scale[CIN];
__device__ __align__(16) float g_shift[CIN];

__device__ __forceinline__ uint32_t pack_h2(float lo, float hi) {
    __half2 h = __floats2half2_rn(lo, hi);
    return *reinterpret_cast<uint32_t*>(&h);
}

__device__ __forceinline__ void mma16816(float& c0, float& c1, float& c2, float& c3,
                                         uint32_t a0, uint32_t a1, uint32_t a2, uint32_t a3,
                                         uint32_t b0, uint32_t b1) {
    asm volatile(
        "mma.sync.aligned.m16n8k16.row.col.f32.f16.f16.f32 "
        "{%0,%1,%2,%3}, {%4,%5,%6,%7}, {%8,%9}, {%0,%1,%2,%3};"
        : "+f"(c0), "+f"(c1), "+f"(c2), "+f"(c3)
        : "r"(a0), "r"(a1), "r"(a2), "r"(a3), "r"(b0), "r"(b1));
}

// ---------------------------------------------------------------------------
// Prep: fold BN into per-channel scale/shift
// ---------------------------------------------------------------------------
__global__ void prep_kernel(const float* __restrict__ gamma, const float* __restrict__ beta,
                            const float* __restrict__ mean,  const float* __restrict__ var) {
    int i = blockIdx.x * blockDim.x + threadIdx.x;
    if (i < CIN) {
        float inv = rsqrtf(var[i] + 1e-5f);
        float s = gamma[i] * inv;
        g_scale[i] = s;
        g_shift[i] = fmaf(-mean[i], s, beta[i]);
    }
}

// ---------------------------------------------------------------------------
// Main GEMM: 256 threads = 8 warps as 2(M) x 4(N); warp tile 64 x 48.
// Double-buffered SMEM; next tile's LDGs issued before the MMA burst.
// ---------------------------------------------------------------------------
__global__ void __launch_bounds__(256, 1)
gemm_kernel(const float* __restrict__ x, const float* __restrict__ W,
            float* __restrict__ out) {
    extern __shared__ char smem[];
    const int tid = threadIdx.x;
    const int l = tid & 31;
    const int w = tid >> 5;
    const int m0 = blockIdx.x * BM;

    // ---- A loader mapping: thread covers rows {rA, rA+64} x k-pairs {kb+4j}
    const int kb = l >> 3;                    // 0..3
    const int rA = (l & 7) + (w << 3);        // 0..63
    int xbase[2];
#pragma unroll
    for (int r = 0; r < 2; r++) {
        int m = m0 + rA + 64 * r;
        int b = m / HWSZ, hw = m - b * HWSZ;
        xbase[r] = b * (CIN * HWSZ) + hw;
    }
    // ---- B loader mapping: thread covers n in {nB, nB+64, nB+128}, k-octet ko
    const int ko = l >> 3;                    // 0..3
    const int nB = (w << 3) + (l & 7);        // 0..63

    // ---- mma mapping
    const int g = l >> 2, t = l & 3;
    const int wm = (w >> 2) * 64;             // warp M offset (0 or 64)
    const int wn = (w & 3) * 48;              // warp N offset

    float acc[4][6][4];
#pragma unroll
    for (int mt = 0; mt < 4; mt++)
#pragma unroll
        for (int nt = 0; nt < 6; nt++)
#pragma unroll
            for (int c = 0; c < 4; c++) acc[mt][nt][c] = 0.0f;

    // stage registers
    float  ar[4][2][2];   // [j][row][k01]
    float4 bw[3][2];      // [i][quad]

    auto ldg_tile = [&](int kt) {
        const int kk = kt * BK;
#pragma unroll
        for (int j = 0; j < 4; j++) {
            const int c0 = kk + (kb + 4 * j) * 2;
            const float* p0 = x + xbase[0] + c0 * HWSZ;
            const float* p1 = x + xbase[1] + c0 * HWSZ;
            ar[j][0][0] = p0[0]; ar[j][0][1] = p0[HWSZ];
            ar[j][1][0] = p1[0]; ar[j][1][1] = p1[HWSZ];
        }
#pragma unroll
        for (int i = 0; i < 3; i++) {
            const float* pw = W + (nB + 64 * i) * CIN + kk + ko * 8;
            bw[i][0] = *reinterpret_cast<const float4*>(pw);
            bw[i][1] = *reinterpret_cast<const float4*>(pw + 4);
        }
    };

    auto sts_tile = [&](int kt, int stage) {
        char* As = smem + stage * A_STAGE;
        char* Bs = smem + SMEM_B0 + stage * B_STAGE;
        const int kk = kt * BK;
#pragma unroll
        for (int j = 0; j < 4; j++) {
            const int c0 = kk + (kb + 4 * j) * 2;
            const float2 sc = *reinterpret_cast<const float2*>(g_scale + c0);
            const float2 sh = *reinterpret_cast<const float2*>(g_shift + c0);
#pragma unroll
            for (int r = 0; r < 2; r++) {
                float v0 = fmaxf(fmaf(ar[j][r][0], sc.x, sh.x), 0.0f);
                float v1 = fmaxf(fmaf(ar[j][r][1], sc.y, sh.y), 0.0f);
                *reinterpret_cast<uint32_t*>(As + (rA + 64 * r) * STRIDE_B + (kb + 4 * j) * 4)
                    = pack_h2(v0, v1);
            }
        }
#pragma unroll
        for (int i = 0; i < 3; i++) {
            uint4 u;
            u.x = pack_h2(bw[i][0].x, bw[i][0].y);
            u.y = pack_h2(bw[i][0].z, bw[i][0].w);
            u.z = pack_h2(bw[i][1].x, bw[i][1].y);
            u.w = pack_h2(bw[i][1].z, bw[i][1].w);
            *reinterpret_cast<uint4*>(Bs + (nB + 64 * i) * STRIDE_B + ko * 16) = u;
        }
    };

    // prologue: tile 0 -> stage 0
    ldg_tile(0);
    sts_tile(0, 0);
    __syncthreads();

#pragma unroll 1
    for (int kt = 0; kt < NKT; kt++) {
        const bool pf = (kt + 1 < NKT);
        if (pf) ldg_tile(kt + 1);             // long-latency loads in flight

        const char* As = smem + (kt & 1) * A_STAGE;
        const char* Bs = smem + SMEM_B0 + (kt & 1) * B_STAGE;
#pragma unroll
        for (int s = 0; s < 2; s++) {         // two k16 steps per BK=32 tile
            const int ksb = s * 32;           // byte offset of k16 step
            uint32_t af[4][4], bf[6][2];
#pragma unroll
            for (int mt = 0; mt < 4; mt++) {
                const char* p = As + (wm + mt * 16 + g) * STRIDE_B + ksb + t * 4;
                af[mt][0] = *reinterpret_cast<const uint32_t*>(p);
                af[mt][1] = *reinterpret_cast<const uint32_t*>(p + 8 * STRIDE_B);
                af[mt][2] = *reinterpret_cast<const uint32_t*>(p + 16);
                af[mt][3] = *reinterpret_cast<const uint32_t*>(p + 8 * STRIDE_B + 16);
            }
#pragma unroll
            for (int nt = 0; nt < 6; nt++) {
                const char* p = Bs + (wn + nt * 8 + g) * STRIDE_B + ksb + t * 4;
                bf[nt][0] = *reinterpret_cast<const uint32_t*>(p);
                bf[nt][1] = *reinterpret_cast<const uint32_t*>(p + 16);
            }
#pragma unroll
            for (int mt = 0; mt < 4; mt++)
#pragma unroll
                for (int nt = 0; nt < 6; nt++)
                    mma16816(acc[mt][nt][0], acc[mt][nt][1], acc[mt][nt][2], acc[mt][nt][3],
                             af[mt][0], af[mt][1], af[mt][2], af[mt][3],
                             bf[nt][0], bf[nt][1]);
        }

        if (pf) sts_tile(kt + 1, (kt + 1) & 1);
        __syncthreads();
    }

    // ---- epilogue: c0,c1 = row g cols 2t,2t+1 ; c2,c3 = row g+8
#pragma unroll
    for (int mt = 0; mt < 4; mt++) {
#pragma unroll
        for (int h = 0; h < 2; h++) {
            const int m = m0 + wm + mt * 16 + g + 8 * h;
            const int b = m / HWSZ, hw = m - b * HWSZ;
            float* op = out + b * (COUT * HWSZ) + hw;
#pragma unroll
            for (int nt = 0; nt < 6; nt++) {
                const int n = wn + nt * 8 + 2 * t;
                op[n * HWSZ]       = acc[mt][nt][2 * h + 0];
                op[(n + 1) * HWSZ] = acc[mt][nt][2 * h + 1];
            }
        }
    }
}

// ---------------------------------------------------------------------------
extern "C" void kernel_launch(void* const* d_in, const int* in_sizes, int n_in,
                              void* d_out, int out_size) {
    (void)in_sizes; (void)n_in; (void)out_size;
    const float* x     = (const float*)d_in[0];
    const float* gamma = (const float*)d_in[1];
    const float* beta  = (const float*)d_in[2];
    const float* rmean = (const float*)d_in[3];
    const float* rvar  = (const float*)d_in[4];
    const float* W     = (const float*)d_in[5];
    float* out = (float*)d_out;

    cudaFuncSetAttribute(gemm_kernel, cudaFuncAttributeMaxDynamicSharedMemorySize, SMEM_TOTAL);

    prep_kernel<<<(CIN + 255) / 256, 256>>>(gamma, beta, rmean, rvar);
    gemm_kernel<<<GRID_M, 256, SMEM_TOTAL>>>(x, W, out);
}